// round 14
// baseline (speedup 1.0000x reference)
#include <cuda_runtime.h>

#define SEQ   550
#define MID   100
#define G3    300   // 3*MID
#define EMBED 10

// Precomputed input-side gate projections gi[t][j] = emb[t]·w_ih[j] + b_ih[j].
// One extra padded row so the per-step prefetch never needs a bounds guard.
__device__ float g_gi[(SEQ + 1) * G3];

// ---------------------------------------------------------------------------
// Kernel 1: embedding lookup + input projection for all timesteps (parallel)
// ---------------------------------------------------------------------------
__global__ void gi_kernel(const int* __restrict__ x,
                          const float* __restrict__ embed,
                          const float* __restrict__ w_ih,
                          const float* __restrict__ b_ih)
{
    const int t = blockIdx.x;     // 0..SEQ-1
    const int j = threadIdx.x;    // 0..G3-1
    const int tok = x[t];
    const float* e = embed + tok * EMBED;
    const float* w = w_ih + j * EMBED;
    float s = b_ih[j];
#pragma unroll
    for (int k = 0; k < EMBED; k++) s = fmaf(e[k], w[k], s);
    g_gi[t * G3 + j] = s;
}

// ---------------------------------------------------------------------------
// Kernel 2: persistent single-block GRU scan.
//
// 10 warps (320 threads). Each gate-row j (0..299) is owned by ONE lane that
// holds all 100 w_hh weights as 50 packed b64 registers; the dot product runs
// on fma.rn.f32x2 (2 MACs/instr) against a 128-bit (ulonglong2) broadcast LDS
// of h -> only 25 smem wavefronts per warp per step.
//
// Triplet layout: warp w, lane 3g+role (g=0..9, role=0/1/2) owns rows
// c, c+100, c+200 for column c = 10w+g. After the matvec, r/z lanes apply
// their sigmoid, the n-lane shfls r and z from its two neighbors, runs the
// tanh/update chain with h_old kept in a register, and stores h_new into the
// OTHER h buffer (double buffering) -> exactly ONE __syncthreads per step.
// ---------------------------------------------------------------------------
__global__ void __launch_bounds__(320, 1)
gru_kernel(const float* __restrict__ hidden,
           const float* __restrict__ w_hh,
           const float* __restrict__ b_hh,
           const float* __restrict__ fc_w,
           const float* __restrict__ fc_b,
           float* __restrict__ out)
{
    __shared__ __align__(16) float sh_h[2][128];   // ping-pong hidden state
    __shared__ float red[16];

    const int tid  = threadIdx.x;
    const int wid  = tid >> 5;
    const int lane = tid & 31;
    const int grp  = lane / 3;            // 0..9 (lanes 30,31 -> 10, idle)
    const int role = lane - grp * 3;      // 0=r, 1=z, 2=n
    const bool act = (lane < 30);
    const int colA = wid * 10 + grp;      // hidden column 0..99 (when act)
    // Idle lanes (30,31) get row <= 209: always in-bounds, results discarded.
    const int row  = act ? (colA + MID * role) : colA;
    const int base = grp * 3;             // lane of role-0 in this triplet

    // --- load this lane's full 100-weight row as 50 packed float pairs ---
    // w_hh rows are 100 floats = 400 bytes -> every row is 16B aligned.
    unsigned long long w2[50];
    {
        const ulonglong2* wp =
            reinterpret_cast<const ulonglong2*>(w_hh + row * MID);
#pragma unroll
        for (int i = 0; i < 25; i++) {
            ulonglong2 v = wp[i];
            w2[2 * i]     = v.x;
            w2[2 * i + 1] = v.y;
        }
    }
    const float bhh = b_hh[row];

    // --- init hidden state (buffer 0) ---
    if (tid < MID) sh_h[0][tid] = hidden[tid];
    float h_old = (act && role == 2) ? hidden[colA] : 0.f;

    // --- gi prefetch for t=0 ---
    const float* gip = g_gi + row;
    float gi = gip[0];
    gip += G3;

    __syncthreads();

#pragma unroll 2
    for (int t = 0; t < SEQ; t++) {
        const float gi_cur = gi;
        gi = *gip;                         // prefetch next step (padded row at t=SEQ-1)
        gip += G3;

        // ---------------- matvec: dot = w_hh[row] · h ----------------
        // 128-bit shared loads: 2 packed f32x2 operands per LDS.
        const ulonglong2* hp =
            reinterpret_cast<const ulonglong2*>(sh_h[t & 1]);
        unsigned long long a0 = 0ull, a1 = 0ull, a2 = 0ull, a3 = 0ull;
#pragma unroll
        for (int i = 0; i < 24; i += 2) {
            ulonglong2 h0 = hp[i];
            ulonglong2 h1 = hp[i + 1];
            asm("fma.rn.f32x2 %0, %1, %2, %0;" : "+l"(a0) : "l"(w2[2 * i    ]), "l"(h0.x));
            asm("fma.rn.f32x2 %0, %1, %2, %0;" : "+l"(a1) : "l"(w2[2 * i + 1]), "l"(h0.y));
            asm("fma.rn.f32x2 %0, %1, %2, %0;" : "+l"(a2) : "l"(w2[2 * i + 2]), "l"(h1.x));
            asm("fma.rn.f32x2 %0, %1, %2, %0;" : "+l"(a3) : "l"(w2[2 * i + 3]), "l"(h1.y));
        }
        {
            ulonglong2 h24 = hp[24];
            asm("fma.rn.f32x2 %0, %1, %2, %0;" : "+l"(a0) : "l"(w2[48]), "l"(h24.x));
            asm("fma.rn.f32x2 %0, %1, %2, %0;" : "+l"(a1) : "l"(w2[49]), "l"(h24.y));
        }

        unsigned long long s01, s23, sp;
        asm("add.rn.f32x2 %0, %1, %2;" : "=l"(s01) : "l"(a0), "l"(a1));
        asm("add.rn.f32x2 %0, %1, %2;" : "=l"(s23) : "l"(a2), "l"(a3));
        asm("add.rn.f32x2 %0, %1, %2;" : "=l"(sp)  : "l"(s01), "l"(s23));
        union { unsigned long long u; float2 f; } cc; cc.u = sp;
        const float pre = (cc.f.x + cc.f.y) + bhh;

        // r/z lanes: fold gi and sigmoid; n-lane keeps raw pre-activation
        float val;
        if (role < 2) {
            const float p2 = pre + gi_cur;
            val = __fdividef(1.f, 1.f + __expf(-p2));
        } else {
            val = pre;
        }

        // triplet exchange within the warp
        const float r = __shfl_sync(0xffffffffu, val, base);
        const float z = __shfl_sync(0xffffffffu, val, base + 1);

        // n-lane: tanh/update chain, store into the other buffer
        if (act && role == 2) {
            const float xa = fmaf(r, pre, gi_cur);        // i_n + r*(Wh+b)
            const float e2 = __expf(2.f * xa);
            const float n  = 1.f - __fdividef(2.f, e2 + 1.f);
            h_old = n + z * (h_old - n);                  // (1-z)*n + z*h
            sh_h[(t + 1) & 1][colA] = h_old;
        }
        __syncthreads();
    }

    // ---------------- epilogue: sigmoid(relu(h) @ fc_w^T + fc_b) ----------------
    const float* hf = sh_h[SEQ & 1];
    float p = 0.f;
    if (tid < MID) p = fmaxf(hf[tid], 0.f) * fc_w[tid];
#pragma unroll
    for (int o = 16; o; o >>= 1) p += __shfl_xor_sync(0xffffffffu, p, o);
    if (lane == 0) red[wid] = p;
    __syncthreads();
    if (tid == 0) {
        float s = fc_b[0];
#pragma unroll
        for (int w = 0; w < 10; w++) s += red[w];
        out[0] = __fdividef(1.f, 1.f + __expf(-s));
    }
}

// ---------------------------------------------------------------------------
// Inputs (metadata order): x, hidden, embed_table, w_ih, w_hh, b_ih, b_hh,
//                          fc_w, fc_b.  Output: float32[1].
// ---------------------------------------------------------------------------
extern "C" void kernel_launch(void* const* d_in, const int* in_sizes, int n_in,
                              void* d_out, int out_size)
{
    const int*   x      = (const int*)  d_in[0];
    const float* hidden = (const float*)d_in[1];
    const float* embed  = (const float*)d_in[2];
    const float* w_ih   = (const float*)d_in[3];
    const float* w_hh   = (const float*)d_in[4];
    const float* b_ih   = (const float*)d_in[5];
    const float* b_hh   = (const float*)d_in[6];
    const float* fc_w   = (const float*)d_in[7];
    const float* fc_b   = (const float*)d_in[8];

    gi_kernel<<<SEQ, G3>>>(x, embed, w_ih, b_ih);
    gru_kernel<<<1, 320>>>(hidden, w_hh, b_hh, fc_w, fc_b, (float*)d_out);
}

// round 15
// speedup vs baseline: 1.0017x; 1.0017x over previous
#include <cuda_runtime.h>

#define SEQ   550
#define MID   100
#define G3    300   // 3*MID
#define EMBED 10

// Precomputed input-side gate projections gi[t][j] = emb[t]·w_ih[j] + b_ih[j].
// One extra padded row so the per-step prefetch never needs a bounds guard.
__device__ float g_gi[(SEQ + 1) * G3];

// ---------------------------------------------------------------------------
// Kernel 1: embedding lookup + input projection for all timesteps (parallel)
// ---------------------------------------------------------------------------
__global__ void gi_kernel(const int* __restrict__ x,
                          const float* __restrict__ embed,
                          const float* __restrict__ w_ih,
                          const float* __restrict__ b_ih)
{
    const int t = blockIdx.x;     // 0..SEQ-1
    const int j = threadIdx.x;    // 0..G3-1
    const int tok = x[t];
    const float* e = embed + tok * EMBED;
    const float* w = w_ih + j * EMBED;
    float s = b_ih[j];
#pragma unroll
    for (int k = 0; k < EMBED; k++) s = fmaf(e[k], w[k], s);
    g_gi[t * G3 + j] = s;
}

// ---------------------------------------------------------------------------
// Kernel 2: persistent single-block GRU scan.
//
// 10 warps (320 threads). Each gate-row j (0..299) is owned by ONE lane that
// holds all 100 w_hh weights as 50 packed b64 registers; the dot product runs
// on fma.rn.f32x2 (2 MACs/instr) against a 128-bit (ulonglong2) broadcast LDS
// of h -> only 25 smem wavefronts per warp per step.
//
// Triplet layout: warp w, lane 3g+role (g=0..9, role=0/1/2) owns rows
// c, c+100, c+200 for column c = 10w+g. After the matvec, r/z lanes apply
// their sigmoid, the n-lane shfls r and z from its two neighbors, runs the
// tanh/update chain with h_old kept in a register, and stores h_new into the
// OTHER h buffer (double buffering) -> exactly ONE __syncthreads per step.
// ---------------------------------------------------------------------------
__global__ void __launch_bounds__(320, 1)
gru_kernel(const float* __restrict__ hidden,
           const float* __restrict__ w_hh,
           const float* __restrict__ b_hh,
           const float* __restrict__ fc_w,
           const float* __restrict__ fc_b,
           float* __restrict__ out)
{
    __shared__ __align__(16) float sh_h[2][128];   // ping-pong hidden state
    __shared__ float red[16];

    const int tid  = threadIdx.x;
    const int wid  = tid >> 5;
    const int lane = tid & 31;
    const int grp  = lane / 3;            // 0..9 (lanes 30,31 -> 10, idle)
    const int role = lane - grp * 3;      // 0=r, 1=z, 2=n
    const bool act = (lane < 30);
    const int colA = wid * 10 + grp;      // hidden column 0..99 (when act)
    // Idle lanes (30,31) get row <= 209: always in-bounds, results discarded.
    const int row  = act ? (colA + MID * role) : colA;
    const int base = grp * 3;             // lane of role-0 in this triplet

    // --- load this lane's full 100-weight row as 50 packed float pairs ---
    // w_hh rows are 100 floats = 400 bytes -> every row is 16B aligned.
    unsigned long long w2[50];
    {
        const ulonglong2* wp =
            reinterpret_cast<const ulonglong2*>(w_hh + row * MID);
#pragma unroll
        for (int i = 0; i < 25; i++) {
            ulonglong2 v = wp[i];
            w2[2 * i]     = v.x;
            w2[2 * i + 1] = v.y;
        }
    }
    const float bhh = b_hh[row];

    // --- init hidden state (buffer 0) ---
    if (tid < MID) sh_h[0][tid] = hidden[tid];
    float h_old = (act && role == 2) ? hidden[colA] : 0.f;

    // --- gi prefetch for t=0 ---
    const float* gip = g_gi + row;
    float gi = gip[0];
    gip += G3;

    __syncthreads();

#pragma unroll 2
    for (int t = 0; t < SEQ; t++) {
        const float gi_cur = gi;
        gi = *gip;                         // prefetch next step (padded row at t=SEQ-1)
        gip += G3;

        // ---------------- matvec: dot = w_hh[row] · h ----------------
        // 128-bit shared loads: 2 packed f32x2 operands per LDS.
        const ulonglong2* hp =
            reinterpret_cast<const ulonglong2*>(sh_h[t & 1]);
        unsigned long long a0 = 0ull, a1 = 0ull, a2 = 0ull, a3 = 0ull;
#pragma unroll
        for (int i = 0; i < 24; i += 2) {
            ulonglong2 h0 = hp[i];
            ulonglong2 h1 = hp[i + 1];
            asm("fma.rn.f32x2 %0, %1, %2, %0;" : "+l"(a0) : "l"(w2[2 * i    ]), "l"(h0.x));
            asm("fma.rn.f32x2 %0, %1, %2, %0;" : "+l"(a1) : "l"(w2[2 * i + 1]), "l"(h0.y));
            asm("fma.rn.f32x2 %0, %1, %2, %0;" : "+l"(a2) : "l"(w2[2 * i + 2]), "l"(h1.x));
            asm("fma.rn.f32x2 %0, %1, %2, %0;" : "+l"(a3) : "l"(w2[2 * i + 3]), "l"(h1.y));
        }
        {
            ulonglong2 h24 = hp[24];
            asm("fma.rn.f32x2 %0, %1, %2, %0;" : "+l"(a0) : "l"(w2[48]), "l"(h24.x));
            asm("fma.rn.f32x2 %0, %1, %2, %0;" : "+l"(a1) : "l"(w2[49]), "l"(h24.y));
        }

        unsigned long long s01, s23, sp;
        asm("add.rn.f32x2 %0, %1, %2;" : "=l"(s01) : "l"(a0), "l"(a1));
        asm("add.rn.f32x2 %0, %1, %2;" : "=l"(s23) : "l"(a2), "l"(a3));
        asm("add.rn.f32x2 %0, %1, %2;" : "=l"(sp)  : "l"(s01), "l"(s23));
        union { unsigned long long u; float2 f; } cc; cc.u = sp;
        const float pre = (cc.f.x + cc.f.y) + bhh;

        // r/z lanes: fold gi and sigmoid; n-lane keeps raw pre-activation
        float val;
        if (role < 2) {
            const float p2 = pre + gi_cur;
            val = __fdividef(1.f, 1.f + __expf(-p2));
        } else {
            val = pre;
        }

        // triplet exchange within the warp
        const float r = __shfl_sync(0xffffffffu, val, base);
        const float z = __shfl_sync(0xffffffffu, val, base + 1);

        // n-lane: tanh/update chain, store into the other buffer
        if (act && role == 2) {
            const float xa = fmaf(r, pre, gi_cur);        // i_n + r*(Wh+b)
            const float e2 = __expf(2.f * xa);
            const float n  = 1.f - __fdividef(2.f, e2 + 1.f);
            h_old = n + z * (h_old - n);                  // (1-z)*n + z*h
            sh_h[(t + 1) & 1][colA] = h_old;
        }
        __syncthreads();
    }

    // ---------------- epilogue: sigmoid(relu(h) @ fc_w^T + fc_b) ----------------
    const float* hf = sh_h[SEQ & 1];
    float p = 0.f;
    if (tid < MID) p = fmaxf(hf[tid], 0.f) * fc_w[tid];
#pragma unroll
    for (int o = 16; o; o >>= 1) p += __shfl_xor_sync(0xffffffffu, p, o);
    if (lane == 0) red[wid] = p;
    __syncthreads();
    if (tid == 0) {
        float s = fc_b[0];
#pragma unroll
        for (int w = 0; w < 10; w++) s += red[w];
        out[0] = __fdividef(1.f, 1.f + __expf(-s));
    }
}

// ---------------------------------------------------------------------------
// Inputs (metadata order): x, hidden, embed_table, w_ih, w_hh, b_ih, b_hh,
//                          fc_w, fc_b.  Output: float32[1].
// ---------------------------------------------------------------------------
extern "C" void kernel_launch(void* const* d_in, const int* in_sizes, int n_in,
                              void* d_out, int out_size)
{
    const int*   x      = (const int*)  d_in[0];
    const float* hidden = (const float*)d_in[1];
    const float* embed  = (const float*)d_in[2];
    const float* w_ih   = (const float*)d_in[3];
    const float* w_hh   = (const float*)d_in[4];
    const float* b_ih   = (const float*)d_in[5];
    const float* b_hh   = (const float*)d_in[6];
    const float* fc_w   = (const float*)d_in[7];
    const float* fc_b   = (const float*)d_in[8];

    gi_kernel<<<SEQ, G3>>>(x, embed, w_ih, b_ih);
    gru_kernel<<<1, 320>>>(hidden, w_hh, b_hh, fc_w, fc_b, (float*)d_out);
}

// round 16
// speedup vs baseline: 1.2267x; 1.2245x over previous
#include <cuda_runtime.h>

#define SEQ   550
#define MID   100
#define G3    300   // 3*MID
#define EMBED 10

// Precomputed input-side gate projections gi[t][j] = emb[t]·w_ih[j] + b_ih[j].
// One extra padded row so the per-step prefetch never needs a bounds guard.
__device__ float g_gi[(SEQ + 1) * G3];

// ---------------------------------------------------------------------------
// Kernel 1: embedding lookup + input projection for all timesteps (parallel)
// ---------------------------------------------------------------------------
__global__ void gi_kernel(const int* __restrict__ x,
                          const float* __restrict__ embed,
                          const float* __restrict__ w_ih,
                          const float* __restrict__ b_ih)
{
    const int t = blockIdx.x;     // 0..SEQ-1
    const int j = threadIdx.x;    // 0..G3-1
    const int tok = x[t];
    const float* e = embed + tok * EMBED;
    const float* w = w_ih + j * EMBED;
    float s = b_ih[j];
#pragma unroll
    for (int k = 0; k < EMBED; k++) s = fmaf(e[k], w[k], s);
    g_gi[t * G3 + j] = s;
}

__device__ __forceinline__ unsigned long long pack2(float lo, float hi) {
    unsigned long long u;
    asm("mov.b64 %0, {%1, %2};" : "=l"(u) : "f"(lo), "f"(hi));
    return u;
}
__device__ __forceinline__ float tanh_mufu(float x) {
    float r;
    asm("tanh.approx.f32 %0, %1;" : "=f"(r) : "f"(x));
    return r;
}

// ---------------------------------------------------------------------------
// Kernel 2: persistent single-block GRU scan.
//
// 20 warps (640 threads), split-k x2. Each gate-row j (0..299) is owned by a
// LANE PAIR: half0 covers h[0..47] (+4 zero-weighted), half1 covers h[48..99],
// both from 16B-aligned bases. 26 FFMA2 per lane, 5 warps per SMSP (perfectly
// balanced) -> worst-SMSP fma issue = 5*26*3 = 390 cyc/step.
//
// Triplet-of-pairs layout: warp w, lane 6g+sub (g=0..4, sub=0..5):
//   role = sub>>1 (0=r,1=z,2=n), half = sub&1, col = 5w+g, row = col+100*role.
// After the matvec + lane-pair shfl reduce, r/z lanes apply sigmoid (MUFU
// tanh), the n0-lane shfls r,z from its triplet, runs the tanh/update chain
// with h_old in a register, and stores h_new into the OTHER buffer
// (double buffering) -> exactly ONE __syncthreads per step.
// ---------------------------------------------------------------------------
__global__ void __launch_bounds__(640, 1)
gru_kernel(const float* __restrict__ hidden,
           const float* __restrict__ w_hh,
           const float* __restrict__ b_hh,
           const float* __restrict__ fc_w,
           const float* __restrict__ fc_b,
           float* __restrict__ out)
{
    __shared__ __align__(16) float sh_h[2][128];   // ping-pong hidden state
    __shared__ float red[24];

    const int tid  = threadIdx.x;
    const int wid  = tid >> 5;
    const int lane = tid & 31;
    const int grp  = lane / 6;            // 0..4 (lanes 30,31 -> 5, idle-ish)
    const int sub  = lane - grp * 6;      // 0..5
    const int half = sub & 1;
    const int role = sub >> 1;            // 0=r, 1=z, 2=n
    const int col  = wid * 5 + grp;       // hidden column (<=100 for idle lanes)
    const int row  = col + MID * role;    // gate row (<=299; idle lanes <=100)
    const int tbase = grp * 6;            // lane of sub0 in this triplet

    // --- load this lane's 52-float weight slice as 26 packed pairs ---
    // half0: w[0..51] with w[48..51] zeroed (covers k=0..47)
    // half1: w[48..99]                      (covers k=48..99)
    // Global base: row*400 + half*192 bytes -> 16B aligned.
    unsigned long long w2[26];
    {
        const float4* wp =
            reinterpret_cast<const float4*>(w_hh + row * MID + half * 48);
#pragma unroll
        for (int i = 0; i < 13; i++) {
            float4 v = wp[i];
            w2[2 * i]     = pack2(v.x, v.y);
            w2[2 * i + 1] = pack2(v.z, v.w);
        }
        if (half == 0) { w2[24] = 0ull; w2[25] = 0ull; }
    }
    // Fold b_hh into the accumulator init; only half0 carries it (added once).
    const float bhh = (half == 0) ? b_hh[row] : 0.f;

    // --- init hidden state (buffer 0) ---
    if (tid < MID) sh_h[0][tid] = hidden[tid];
    float h_old = (sub == 4) ? hidden[col] : 0.f;

    // --- gi prefetch for t=0 (r/z lanes keep gi pre-halved for the sigmoid) ---
    const float gi_scale = (role < 2) ? 0.5f : 1.0f;
    const float* gip = g_gi + row;
    float gi = gip[0] * gi_scale;
    gip += G3;

    __syncthreads();

#pragma unroll 2
    for (int t = 0; t < SEQ; t++) {
        const float gi_cur = gi;
        gi = (*gip) * gi_scale;            // prefetch next (padded row at t=SEQ-1)
        gip += G3;

        // ---------------- matvec: dot = w_hh[row] · h (this lane's half) ----
        const ulonglong2* hp = reinterpret_cast<const ulonglong2*>(
            reinterpret_cast<const char*>(sh_h[t & 1]) + half * 192);
        unsigned long long a0 = pack2(bhh, 0.f);
        unsigned long long a1 = 0ull, a2 = 0ull, a3 = 0ull;
#pragma unroll
        for (int i = 0; i < 12; i += 2) {
            ulonglong2 h0 = hp[i];
            ulonglong2 h1 = hp[i + 1];
            asm("fma.rn.f32x2 %0, %1, %2, %0;" : "+l"(a0) : "l"(w2[2 * i    ]), "l"(h0.x));
            asm("fma.rn.f32x2 %0, %1, %2, %0;" : "+l"(a1) : "l"(w2[2 * i + 1]), "l"(h0.y));
            asm("fma.rn.f32x2 %0, %1, %2, %0;" : "+l"(a2) : "l"(w2[2 * i + 2]), "l"(h1.x));
            asm("fma.rn.f32x2 %0, %1, %2, %0;" : "+l"(a3) : "l"(w2[2 * i + 3]), "l"(h1.y));
        }
        {
            ulonglong2 h12 = hp[12];
            asm("fma.rn.f32x2 %0, %1, %2, %0;" : "+l"(a0) : "l"(w2[24]), "l"(h12.x));
            asm("fma.rn.f32x2 %0, %1, %2, %0;" : "+l"(a1) : "l"(w2[25]), "l"(h12.y));
        }
        unsigned long long s01, s23, sp;
        asm("add.rn.f32x2 %0, %1, %2;" : "=l"(s01) : "l"(a0), "l"(a1));
        asm("add.rn.f32x2 %0, %1, %2;" : "=l"(s23) : "l"(a2), "l"(a3));
        asm("add.rn.f32x2 %0, %1, %2;" : "=l"(sp)  : "l"(s01), "l"(s23));
        union { unsigned long long u; float2 f; } cc; cc.u = sp;
        float s = cc.f.x + cc.f.y;
        s += __shfl_xor_sync(0xffffffffu, s, 1);   // combine the two k-halves
        const float pre = s;                        // full dot + b_hh

        // r/z lanes: sigmoid(pre + gi) = 0.5*tanh(0.5*pre + 0.5*gi) + 0.5
        float val;
        if (role < 2) {
            val = fmaf(0.5f, tanh_mufu(fmaf(0.5f, pre, gi_cur)), 0.5f);
        } else {
            val = pre;
        }

        // triplet exchange within the warp
        const float r = __shfl_sync(0xffffffffu, val, tbase);
        const float z = __shfl_sync(0xffffffffu, val, tbase + 2);

        // n0-lane: tanh/update chain, store into the other buffer
        if (sub == 4) {
            const float xa = fmaf(r, pre, gi_cur);   // i_n + r*(Wh+b)
            const float n  = tanh_mufu(xa);
            h_old = n + z * (h_old - n);             // (1-z)*n + z*h
            sh_h[(t + 1) & 1][col] = h_old;
        }
        __syncthreads();
    }

    // ---------------- epilogue: sigmoid(relu(h) @ fc_w^T + fc_b) ----------------
    const float* hf = sh_h[SEQ & 1];
    float p = 0.f;
    if (tid < MID) p = fmaxf(hf[tid], 0.f) * fc_w[tid];
#pragma unroll
    for (int o = 16; o; o >>= 1) p += __shfl_xor_sync(0xffffffffu, p, o);
    if (lane == 0) red[wid] = p;
    __syncthreads();
    if (tid == 0) {
        float sfin = fc_b[0];
#pragma unroll
        for (int w = 0; w < 20; w++) sfin += red[w];
        out[0] = __fdividef(1.f, 1.f + __expf(-sfin));
    }
}

// ---------------------------------------------------------------------------
// Inputs (metadata order): x, hidden, embed_table, w_ih, w_hh, b_ih, b_hh,
//                          fc_w, fc_b.  Output: float32[1].
// ---------------------------------------------------------------------------
extern "C" void kernel_launch(void* const* d_in, const int* in_sizes, int n_in,
                              void* d_out, int out_size)
{
    const int*   x      = (const int*)  d_in[0];
    const float* hidden = (const float*)d_in[1];
    const float* embed  = (const float*)d_in[2];
    const float* w_ih   = (const float*)d_in[3];
    const float* w_hh   = (const float*)d_in[4];
    const float* b_ih   = (const float*)d_in[5];
    const float* b_hh   = (const float*)d_in[6];
    const float* fc_w   = (const float*)d_in[7];
    const float* fc_b   = (const float*)d_in[8];

    gi_kernel<<<SEQ, G3>>>(x, embed, w_ih, b_ih);
    gru_kernel<<<1, 640>>>(hidden, w_hh, b_hh, fc_w, fc_b, (float*)d_out);
}